// round 15
// baseline (speedup 1.0000x reference)
#include <cuda_runtime.h>
#include <cstdint>

#define BB 4
#define NN 16384
#define SS 4096
#define CC 64
#define NS 64
#define OUTC 67   // 3 + C

// Scratch (device globals — no allocation allowed)
__device__ float g_feat_t[BB * NN * CC];   // features transposed to (B, N, C)
__device__ int   g_idx[BB * SS * NS];      // ball-query result indices

// ---------------------------------------------------------------------------
// Kernel 1: transpose features (B, C, N) -> (B, N, C)
// ---------------------------------------------------------------------------
__global__ void transpose_kernel(const float* __restrict__ feat) {
    __shared__ float tile[32][33];
    int b  = blockIdx.z;
    int n0 = blockIdx.x * 32;
    int c0 = blockIdx.y * 32;
    int tx = threadIdx.x, ty = threadIdx.y;   // block (32, 8)
    #pragma unroll
    for (int i = 0; i < 32; i += 8)
        tile[ty + i][tx] = feat[((size_t)(b * CC + c0 + ty + i) * NN) + n0 + tx];
    __syncthreads();
    #pragma unroll
    for (int i = 0; i < 32; i += 8)
        g_feat_t[((size_t)(b * NN + n0 + ty + i) * CC) + c0 + tx] = tile[tx][ty + i];
}

// ---------------------------------------------------------------------------
// Kernel 2: ball query — one warp per query point.
// Ladder rung 6 — LLVM DAGCombiner FMA-contraction pattern (XLA CPU):
//   fadd(fmul(x,x), fmul(y,y)) fuses the FIRST operand:
//     s1 = fma(x,x, RN(y·y)) ; s2 = fma(z,z, s1)
//   Applied uniformly to q2, p2, and the strength-reduced K=3 dot qp:
//     q2 = fma(z,z,  fma(x,x,  RN(y·y)))
//     qp = fma(z,z', fma(x,x', RN(y·y')))
//   d2 = (q2 + p2) - (2*qp)   [rounding unique — proven]
// Threshold: f32(0.04).
// ---------------------------------------------------------------------------
__global__ __launch_bounds__(256) void ballquery_kernel(
    const float* __restrict__ xyz, const float* __restrict__ new_xyz) {
    const float R2 = 0.04f;  // 0.039999999105930328f
    int warp = (blockIdx.x * blockDim.x + threadIdx.x) >> 5;
    int lane = threadIdx.x & 31;
    if (warp >= BB * SS) return;
    int b = warp / SS;
    const float* q = new_xyz + (size_t)warp * 3;
    float xq = q[0], yq = q[1], zq = q[2];
    // q2: LLVM-contracted chain — y term rounded, x and z fused
    float q2 = fmaf(zq, zq, fmaf(xq, xq, __fmul_rn(yq, yq)));
    const float* px = xyz + (size_t)b * NN * 3;
    int* out = g_idx + (size_t)warp * NS;

    int cnt = 0;
    int first = 0;
    for (int n0 = 0; n0 < NN; n0 += 32) {
        int n = n0 + lane;
        float xp = px[n * 3 + 0];
        float yp = px[n * 3 + 1];
        float zp = px[n * 3 + 2];
        // p2: LLVM-contracted chain
        float p2 = fmaf(zp, zp, fmaf(xp, xp, __fmul_rn(yp, yp)));
        // qp: LLVM-contracted chain — fma(z,z', fma(x,x', RN(y·y')))
        float qp = fmaf(zq, zp, fmaf(xq, xp, __fmul_rn(yq, yp)));
        float d2 = __fsub_rn(__fadd_rn(q2, p2), __fmul_rn(2.0f, qp));
        bool in = d2 < R2;
        unsigned mask = __ballot_sync(0xffffffffu, in);
        if (cnt == 0 && mask) first = n0 + __ffs(mask) - 1;
        if (in) {
            int pos = cnt + __popc(mask & ((1u << lane) - 1u));
            if (pos < NS) out[pos] = n;
        }
        cnt += __popc(mask);
        if (cnt >= NS) break;
    }
    if (cnt < NS) {
        int fill = (cnt > 0) ? first : 0;
        for (int k = cnt + lane; k < NS; k += 32) out[k] = fill;
    }
}

// ---------------------------------------------------------------------------
// Kernel 3: grouping — one block (256 thr) per query.
// Gather 64 points x 64 channels from transposed features (contiguous 256B
// per point, float4 loads), plus xyz-minus-center; stage in shared with
// stride-69 padding (conflict-free column reads); write out coalesced.
// Output layout: (B, 3+C, S, NS)
// ---------------------------------------------------------------------------
__global__ __launch_bounds__(256) void group_kernel(
    const float* __restrict__ xyz, const float* __restrict__ new_xyz,
    float* __restrict__ out) {
    __shared__ float tile[NS][69];   // [point][channel], padded
    __shared__ int   sidx[NS];

    int qidx = blockIdx.x;           // 0 .. B*S-1
    int b = qidx / SS, s = qidx % SS;
    int tid = threadIdx.x;

    if (tid < NS) sidx[tid] = g_idx[(size_t)qidx * NS + tid];
    __syncthreads();

    // Gather features: 64 points x 16 float4 each = 1024 slots
    const float* ft = g_feat_t + (size_t)b * NN * CC;
    #pragma unroll
    for (int it = 0; it < 4; ++it) {
        int slot = tid + it * 256;
        int p = slot >> 4;           // point 0..63
        int v = slot & 15;           // float4 index 0..15
        float4 f = *(const float4*)(ft + (size_t)sidx[p] * CC + v * 4);
        float* dst = &tile[p][3 + v * 4];
        dst[0] = f.x; dst[1] = f.y; dst[2] = f.z; dst[3] = f.w;
    }

    // xyz part: grouped_xyz - center
    if (tid < NS) {
        const float* xp = xyz + (size_t)(b * NN + sidx[tid]) * 3;
        const float* qq = new_xyz + (size_t)(b * SS + s) * 3;
        tile[tid][0] = __fsub_rn(xp[0], qq[0]);
        tile[tid][1] = __fsub_rn(xp[1], qq[1]);
        tile[tid][2] = __fsub_rn(xp[2], qq[2]);
    }
    __syncthreads();

    // Write out: 67 channels x 64 samples = 4288 floats, coalesced per channel row
    for (int slot = tid; slot < OUTC * NS; slot += 256) {
        int c = slot >> 6;
        int k = slot & 63;
        out[(((size_t)b * OUTC + c) * SS + s) * NS + k] = tile[k][c];
    }
}

// ---------------------------------------------------------------------------
extern "C" void kernel_launch(void* const* d_in, const int* in_sizes, int n_in,
                              void* d_out, int out_size) {
    const float* xyz      = (const float*)d_in[0];   // (B, N, 3)
    const float* new_xyz  = (const float*)d_in[1];   // (B, S, 3)
    const float* features = (const float*)d_in[2];   // (B, C, N)
    float* out = (float*)d_out;                      // (B, 3+C, S, NS)

    dim3 tgrid(NN / 32, CC / 32, BB);
    transpose_kernel<<<tgrid, dim3(32, 8)>>>(features);

    int warps = BB * SS;                    // one warp per query
    int threads = 256;
    int blocks = (warps * 32 + threads - 1) / threads;
    ballquery_kernel<<<blocks, threads>>>(xyz, new_xyz);

    group_kernel<<<BB * SS, 256>>>(xyz, new_xyz, out);
}